// round 13
// baseline (speedup 1.0000x reference)
#include <cuda_runtime.h>
#include <cuda_fp16.h>
#include <math.h>

#define NN 8192
#define NB 32
#define NG 256
#define NE 65536
#define DK 512
#define HH 32
#define VB 2048
#define VF 512
#define EPS 1e-5f

// ---------------- device scratch ----------------
__device__ float g_sB[NN], g_sF[NN];
__device__ __half2 g_vnB[NN * VB / 2];   // normalized visual_body fp16 (32 MB)
__device__ __half2 g_vnF[NN * VF / 2];   // normalized visual_face fp16 (8 MB)
__device__ float g_P0[DK], g_P1[DK];
__device__ float g_M1[DK], g_M2[DK], g_M3[DK];
__device__ float g_cst[12];
// edge sort scratch (counters zeroed by edge_kernel for next replay; zero at load)
__device__ int g_cntB[NN], g_cntF[NN];
__device__ int g_curB[NN], g_curF[NN];
__device__ int2 g_edB[NE], g_edF[NE];    // dst-sorted (src,dst)
__device__ float g_pad_[32];
__device__ volatile int g_flag = 0;      // constants ready
__device__ volatile int g_hist_done = 0; // hist blocks finished (target 64)
__device__ volatile int g_scan_done = 0; // scan blocks finished (target 2)

__device__ __forceinline__ float warpSum(float v) {
    #pragma unroll
    for (int o = 16; o; o >>= 1) v += __shfl_xor_sync(0xFFFFFFFFu, v, o);
    return v;
}

// ---------------- K1 grid layout (256 threads per block) ----------------
// 0                : precompute constants -> g_flag
// [1, 65)          : edge histograms (both graphs), bump g_hist_done
// [65, 1089)       : attention + node (spin g_flag)
// [1089, 2113)     : body norm (warp/row, register prefetch)  -- R8 proven
// [2113, 3137)     : face norm (warp/row)
// [3137, 3139)     : exclusive scan of 8192 bins (spin hist), bump g_scan_done
// [3139, 3203)     : scatter edges into sorted order (spin scan)
#define BLK_PRE    0
#define BLK_HIST   1
#define BLK_ATTN   (BLK_HIST + 64)
#define BLK_NBODY  (BLK_ATTN + 1024)
#define BLK_NFACE  (BLK_NBODY + 1024)
#define BLK_SCAN   (BLK_NFACE + 1024)
#define BLK_SCAT   (BLK_SCAN + 2)
#define GRID_K1    (BLK_SCAT + 64)

__global__ __launch_bounds__(256)
void norm_attn_kernel(const float* __restrict__ visB, const float* __restrict__ visF,
                      const float* __restrict__ x,
                      const float* __restrict__ ln_g, const float* __restrict__ ln_b,
                      const float* __restrict__ prelu_a,
                      const float* __restrict__ Wq, const float* __restrict__ Wk,
                      const float* __restrict__ Wv,
                      const float* __restrict__ mlp_W, const float* __restrict__ mlp_b,
                      const float* __restrict__ np_W, const float* __restrict__ np_b,
                      const float* __restrict__ body_W, const float* __restrict__ body_b,
                      const float* __restrict__ face_W, const float* __restrict__ face_b,
                      const float* __restrict__ pb_W, const float* __restrict__ pb_b,
                      const float* __restrict__ pf_W, const float* __restrict__ pf_b,
                      const int* __restrict__ eiB, const int* __restrict__ eiF,
                      float* __restrict__ out) {
    int b = blockIdx.x;
    int t = threadIdx.x;
    int lane = t & 31;
    int warp = t >> 5;

    if (b == BLK_PRE) {
        // ---------------- precompute constants ----------------
        __shared__ float sh_u2[HH], sh_u3[HH], sh_np[HH];
        __shared__ float sh_part[8][9];
        __shared__ float sh_res[12];
        int k1 = t, k2 = t + 256;

        if (t < HH) {
            float a2 = 0.f, a3 = 0.f;
            #pragma unroll
            for (int j = 0; j < HH; ++j) {
                a2 += body_W[t * HH + j] * pb_W[j];
                a3 += face_W[t * HH + j] * pf_W[j];
            }
            sh_u2[t] = a2;
            sh_u3[t] = a3;
            sh_np[t] = np_W[t];
        }

        float wq0a = Wq[k1], wq0b = Wq[k2], wq1a = Wq[DK + k1], wq1b = Wq[DK + k2];
        float wk0a = Wk[k1], wk0b = Wk[k2], wk1a = Wk[DK + k1], wk1b = Wk[DK + k2];
        float wv0a = Wv[k1], wv0b = Wv[k2], wv1a = Wv[DK + k1], wv1b = Wv[DK + k2];

        float v0 = warpSum(wq0a * wk0a + wq0b * wk0b);
        float v1 = warpSum(wq0a * wk1a + wq0b * wk1b);
        float v2 = warpSum(wq1a * wk0a + wq1b * wk0b);
        float v3 = warpSum(wq1a * wk1a + wq1b * wk1b);
        float v4 = warpSum(wv0a + wv0b);
        float v5 = warpSum(wv1a + wv1b);
        float v6 = warpSum(wv0a * wv0a + wv0b * wv0b);
        float v7 = warpSum(wv0a * wv1a + wv0b * wv1b);
        float v8 = warpSum(wv1a * wv1a + wv1b * wv1b);
        if (lane == 0) {
            sh_part[warp][0] = v0; sh_part[warp][1] = v1; sh_part[warp][2] = v2;
            sh_part[warp][3] = v3; sh_part[warp][4] = v4; sh_part[warp][5] = v5;
            sh_part[warp][6] = v6; sh_part[warp][7] = v7; sh_part[warp][8] = v8;
        }
        __syncthreads();

        if (warp == 0) {
            float mb = mlp_b[lane];
            float b1 = warpSum(mb * sh_np[lane]);
            float b2 = warpSum(mb * sh_u2[lane]);
            float b3 = warpSum(mb * sh_u3[lane]);
            float vBv = warpSum(body_b[lane] * pb_W[lane]);
            float vFv = warpSum(face_b[lane] * pf_W[lane]);
            if (lane == 0) {
                float r[9];
                #pragma unroll
                for (int i = 0; i < 9; ++i) {
                    float s = 0.f;
                    #pragma unroll
                    for (int w = 0; w < 8; ++w) s += sh_part[w][i];
                    r[i] = s;
                }
                float m0 = r[4] / (float)DK, m1 = r[5] / (float)DK;
                sh_res[0] = r[0]; sh_res[1] = r[1]; sh_res[2] = r[2]; sh_res[3] = r[3];
                sh_res[4] = r[6] / (float)DK - m0 * m0;
                sh_res[5] = r[7] / (float)DK - m0 * m1;
                sh_res[6] = r[8] / (float)DK - m1 * m1;
                sh_res[7] = b1 + np_b[0] + pb_b[0] + pf_b[0];
                sh_res[8] = b2 + vBv;
                sh_res[9] = b3 + vFv;
                sh_res[10] = m0;
                sh_res[11] = m1;
            }
        }
        __syncthreads();

        if (t < 12) g_cst[t] = sh_res[t];
        g_P0[k1] = wv0a - sh_res[10];
        g_P0[k2] = wv0b - sh_res[10];
        g_P1[k1] = wv1a - sh_res[11];
        g_P1[k2] = wv1b - sh_res[11];

        float a1a = 0.f, a2a = 0.f, a3a = 0.f, a1b = 0.f, a2b = 0.f, a3b = 0.f;
        #pragma unroll
        for (int l = 0; l < HH; ++l) {
            float wa = mlp_W[k1 * HH + l];
            float wb = mlp_W[k2 * HH + l];
            float un = sh_np[l], u2 = sh_u2[l], u3 = sh_u3[l];
            a1a += wa * un; a2a += wa * u2; a3a += wa * u3;
            a1b += wb * un; a2b += wb * u2; a3b += wb * u3;
        }
        g_M1[k1] = a1a; g_M2[k1] = a2a; g_M3[k1] = a3a;
        g_M1[k2] = a1b; g_M2[k2] = a2b; g_M3[k2] = a3b;

        __threadfence();
        __syncthreads();
        if (t == 0) g_flag = 1;
    } else if (b < BLK_ATTN) {
        // ---------------- edge histograms (both graphs) ----------------
        int h = b - BLK_HIST;            // 0..63, each covers 1024 edges per list
        #pragma unroll
        for (int i = 0; i < 4; ++i) {
            int e = h * 1024 + i * 256 + t;
            atomicAdd(&g_cntB[eiB[NE + e]], 1);
            atomicAdd(&g_cntF[eiF[NE + e]], 1);
        }
        __threadfence();
        __syncthreads();
        if (t == 0) atomicAdd((int*)&g_hist_done, 1);
    } else if (b < BLK_NBODY) {
        // ---------------- attention + node stage (spin g_flag) ----------------
        __shared__ float sa[NG], sb[NG];
        int idx = b - BLK_ATTN;
        int g = idx >> 5;
        int bi = idx & 31;
        int node = g * NG + t;
        sa[t] = x[2 * node];
        sb[t] = x[2 * node + 1];
        if (t == 0) {
            while (g_flag == 0) {}
        }
        __syncthreads();
        __threadfence();

        float g00 = g_cst[0], g01 = g_cst[1], g10 = g_cst[2], g11 = g_cst[3];
        const float inv = 0.04419417382415922f;
        int i = bi * 8 + warp;

        float ai = sa[i], bi2 = sb[i];
        float alpha = (ai * g00 + bi2 * g10) * inv;
        float beta  = (ai * g01 + bi2 * g11) * inv;
        float m = -1e30f;
        #pragma unroll
        for (int j = lane; j < NG; j += 32)
            m = fmaxf(m, alpha * sa[j] + beta * sb[j]);
        #pragma unroll
        for (int o = 16; o; o >>= 1) m = fmaxf(m, __shfl_xor_sync(0xFFFFFFFFu, m, o));
        float s = 0.f, sA = 0.f, sBv = 0.f;
        #pragma unroll
        for (int j = lane; j < NG; j += 32) {
            float e = __expf(alpha * sa[j] + beta * sb[j] - m);
            s += e; sA += e * sa[j]; sBv += e * sb[j];
        }
        s = warpSum(s); sA = warpSum(sA); sBv = warpSum(sBv);
        float c = sA / s, d = sBv / s;

        float s00 = g_cst[4], s01 = g_cst[5], s11 = g_cst[6];
        float var = c * c * s00 + 2.f * c * d * s01 + d * d * s11;
        float rstd = rsqrtf(var + EPS);
        float a = prelu_a[0];
        float acc1 = 0.f, acc2 = 0.f, acc3 = 0.f;
        #pragma unroll 4
        for (int k = lane; k < DK; k += 32) {
            float z = (c * g_P0[k] + d * g_P1[k]) * rstd;
            float tv = z * ln_g[k] + ln_b[k];
            tv = tv >= 0.f ? tv : a * tv;
            acc1 += tv * g_M1[k];
            acc2 += tv * g_M2[k];
            acc3 += tv * g_M3[k];
        }
        acc1 = warpSum(acc1); acc2 = warpSum(acc2); acc3 = warpSum(acc3);
        if (lane == 0) {
            int n = g * NG + i;
            out[n]  = acc1 + g_cst[7];
            g_sB[n] = acc2 + g_cst[8];
            g_sF[n] = acc3 + g_cst[9];
        }
    } else if (b < BLK_NFACE) {
        // ---------------- body norm: warp per row, register prefetch (R8 proven) ----------------
        int row = ((b - BLK_NBODY) * 256 + t) >> 5;
        const float4* v = reinterpret_cast<const float4*>(visB) + (size_t)row * (VB / 4) + lane;
        float4 r[16];
        #pragma unroll
        for (int i = 0; i < 16; ++i) r[i] = v[i * 32];
        float acc = 0.f;
        #pragma unroll
        for (int i = 0; i < 16; ++i)
            acc += r[i].x * r[i].x + r[i].y * r[i].y + r[i].z * r[i].z + r[i].w * r[i].w;
        acc = warpSum(acc);
        float rs = rsqrtf(acc + 1e-8f);
        uint2* o = reinterpret_cast<uint2*>(g_vnB) + (size_t)row * (VB / 4) + lane;
        #pragma unroll
        for (int i = 0; i < 16; ++i) {
            __half2 h0 = __floats2half2_rn(r[i].x * rs, r[i].y * rs);
            __half2 h1 = __floats2half2_rn(r[i].z * rs, r[i].w * rs);
            uint2 u;
            u.x = *reinterpret_cast<unsigned*>(&h0);
            u.y = *reinterpret_cast<unsigned*>(&h1);
            o[i * 32] = u;
        }
    } else if (b < BLK_SCAN) {
        // ---------------- face norm: warp per row ----------------
        int row = ((b - BLK_NFACE) * 256 + t) >> 5;
        const float4* v = reinterpret_cast<const float4*>(visF) + (size_t)row * (VF / 4) + lane;
        float4 r[4];
        #pragma unroll
        for (int i = 0; i < 4; ++i) r[i] = v[i * 32];
        float acc = 0.f;
        #pragma unroll
        for (int i = 0; i < 4; ++i)
            acc += r[i].x * r[i].x + r[i].y * r[i].y + r[i].z * r[i].z + r[i].w * r[i].w;
        acc = warpSum(acc);
        float rs = rsqrtf(acc + 1e-8f);
        uint2* o = reinterpret_cast<uint2*>(g_vnF) + (size_t)row * (VF / 4) + lane;
        #pragma unroll
        for (int i = 0; i < 4; ++i) {
            __half2 h0 = __floats2half2_rn(r[i].x * rs, r[i].y * rs);
            __half2 h1 = __floats2half2_rn(r[i].z * rs, r[i].w * rs);
            uint2 u;
            u.x = *reinterpret_cast<unsigned*>(&h0);
            u.y = *reinterpret_cast<unsigned*>(&h1);
            o[i * 32] = u;
        }
    } else if (b < BLK_SCAT) {
        // ---------------- exclusive scan of 8192 bins (block 0: body, 1: face) ----------------
        __shared__ int sh[256];
        const int* cnt = (b == BLK_SCAN) ? g_cntB : g_cntF;
        int* cur = (b == BLK_SCAN) ? g_curB : g_curF;
        if (t == 0) {
            while (g_hist_done < 64) {}
        }
        __syncthreads();
        __threadfence();
        int base = t * 32;
        int s = 0;
        #pragma unroll 8
        for (int i = 0; i < 32; ++i) s += cnt[base + i];
        sh[t] = s;
        __syncthreads();
        for (int o = 1; o < 256; o <<= 1) {
            int v = (t >= o) ? sh[t - o] : 0;
            __syncthreads();
            sh[t] += v;
            __syncthreads();
        }
        int excl = (t == 0) ? 0 : sh[t - 1];
        #pragma unroll 8
        for (int i = 0; i < 32; ++i) {
            cur[base + i] = excl;
            excl += cnt[base + i];
        }
        __threadfence();
        __syncthreads();
        if (t == 0) atomicAdd((int*)&g_scan_done, 1);
    } else {
        // ---------------- scatter edges into dst-sorted order ----------------
        int h = b - BLK_SCAT;            // 0..63
        if (t == 0) {
            while (g_scan_done < 2) {}
        }
        __syncthreads();
        __threadfence();
        #pragma unroll
        for (int i = 0; i < 4; ++i) {
            int e = h * 1024 + i * 256 + t;
            int srcB = eiB[e], dstB = eiB[NE + e];
            int pB = atomicAdd(&g_curB[dstB], 1);
            if (pB < NE) g_edB[pB] = make_int2(srcB, dstB);
            int srcF = eiF[e], dstF = eiF[NE + e];
            int pF = atomicAdd(&g_curF[dstF], 1);
            if (pF < NE) g_edF[pF] = make_int2(srcF, dstF);
        }
    }
}

// ---------------- K_edge: dst-sorted, deep prefetch ----------------
#define EDGE_TPB 128
#define BODY_WARPS NE                 // 65536 warps
#define FACE_WARPS (NE / 2)           // 32768 warps
#define BODY_BLOCKS (BODY_WARPS * 32 / EDGE_TPB)   // 16384
#define FACE_BLOCKS (FACE_WARPS * 32 / EDGE_TPB)   // 8192

__global__ void edge_kernel(float* __restrict__ out) {
    // reset sync state + bin counters for the next graph replay
    if (blockIdx.x < 64) {
        int i = blockIdx.x * EDGE_TPB + threadIdx.x;   // 8192 threads
        g_cntB[i] = 0;
        g_cntF[i] = 0;
        if (i == 0) { g_flag = 0; g_hist_done = 0; g_scan_done = 0; }
    }

    int gw = (blockIdx.x * EDGE_TPB + threadIdx.x) >> 5;
    int lane = threadIdx.x & 31;

    if (gw < BODY_WARPS) {
        int2 ed = g_edB[gw];
        int src = ed.x, dst = ed.y;
        const int4* a = reinterpret_cast<const int4*>(g_vnB) + (size_t)src * (VB / 8) + lane;
        const int4* b = reinterpret_cast<const int4*>(g_vnB) + (size_t)dst * (VB / 8) + lane;
        int4 ra[8], rb[8];
        #pragma unroll
        for (int i = 0; i < 8; ++i) ra[i] = a[i * 32];
        #pragma unroll
        for (int i = 0; i < 8; ++i) rb[i] = b[i * 32];
        float acc0 = 0.f, acc1 = 0.f;
        #pragma unroll
        for (int i = 0; i < 8; ++i) {
            const __half2* ha = reinterpret_cast<const __half2*>(&ra[i]);
            const __half2* hb = reinterpret_cast<const __half2*>(&rb[i]);
            #pragma unroll
            for (int u = 0; u < 4; ++u) {
                float2 fa = __half22float2(ha[u]);
                float2 fb = __half22float2(hb[u]);
                acc0 += fa.x * fb.x;
                acc1 += fa.y * fb.y;
            }
        }
        float acc = warpSum(acc0 + acc1);
        if (lane == 0) atomicAdd(&out[dst], acc * g_sB[src]);
    } else {
        int e = (gw - BODY_WARPS) * 2 + (lane >> 4);
        int hl = lane & 15;
        int2 ed = g_edF[e];
        int src = ed.x, dst = ed.y;
        const int4* a = reinterpret_cast<const int4*>(g_vnF) + (size_t)src * (VF / 8) + hl;
        const int4* b = reinterpret_cast<const int4*>(g_vnF) + (size_t)dst * (VF / 8) + hl;
        int4 ra[4], rb[4];
        #pragma unroll
        for (int i = 0; i < 4; ++i) ra[i] = a[i * 16];
        #pragma unroll
        for (int i = 0; i < 4; ++i) rb[i] = b[i * 16];
        float acc0 = 0.f, acc1 = 0.f;
        #pragma unroll
        for (int i = 0; i < 4; ++i) {
            const __half2* ha = reinterpret_cast<const __half2*>(&ra[i]);
            const __half2* hb = reinterpret_cast<const __half2*>(&rb[i]);
            #pragma unroll
            for (int u = 0; u < 4; ++u) {
                float2 fa = __half22float2(ha[u]);
                float2 fb = __half22float2(hb[u]);
                acc0 += fa.x * fb.x;
                acc1 += fa.y * fb.y;
            }
        }
        float acc = acc0 + acc1;
        #pragma unroll
        for (int o = 8; o; o >>= 1) acc += __shfl_xor_sync(0xFFFFFFFFu, acc, o);
        if (hl == 0) atomicAdd(&out[dst], acc * g_sF[src]);
    }
}

// ---------------- launch ----------------
extern "C" void kernel_launch(void* const* d_in, const int* in_sizes, int n_in,
                              void* d_out, int out_size) {
    const float* x           = (const float*)d_in[0];
    const float* visual_body = (const float*)d_in[1];
    const float* visual_face = (const float*)d_in[2];
    const float* Wq          = (const float*)d_in[3];
    const float* Wk          = (const float*)d_in[4];
    const float* Wv          = (const float*)d_in[5];
    const float* ln_g        = (const float*)d_in[6];
    const float* ln_b        = (const float*)d_in[7];
    const float* prelu_a     = (const float*)d_in[8];
    const float* mlp_W       = (const float*)d_in[9];
    const float* mlp_b       = (const float*)d_in[10];
    const float* np_W        = (const float*)d_in[11];
    const float* np_b        = (const float*)d_in[12];
    const float* body_W      = (const float*)d_in[13];
    const float* body_b      = (const float*)d_in[14];
    const float* face_W      = (const float*)d_in[15];
    const float* face_b      = (const float*)d_in[16];
    const float* pb_W        = (const float*)d_in[17];
    const float* pb_b        = (const float*)d_in[18];
    const float* pf_W        = (const float*)d_in[19];
    const float* pf_b        = (const float*)d_in[20];
    const int*   ei_body     = (const int*)d_in[21];
    const int*   ei_face     = (const int*)d_in[22];
    float* out = (float*)d_out;

    norm_attn_kernel<<<GRID_K1, 256>>>(
        visual_body, visual_face, x, ln_g, ln_b, prelu_a,
        Wq, Wk, Wv, mlp_W, mlp_b, np_W, np_b,
        body_W, body_b, face_W, face_b, pb_W, pb_b, pf_W, pf_b,
        ei_body, ei_face, out);

    edge_kernel<<<BODY_BLOCKS + FACE_BLOCKS, EDGE_TPB>>>(out);
}

// round 14
// speedup vs baseline: 1.3558x; 1.3558x over previous
#include <cuda_runtime.h>
#include <cuda_fp16.h>
#include <math.h>

#define NN 8192
#define NB 32
#define NG 256
#define NE 65536
#define DK 512
#define HH 32
#define VB 2048
#define VF 512
#define EPS 1e-5f

// ---------------- device scratch ----------------
__device__ float g_sB[NN], g_sF[NN];
__device__ __half2 g_vnB[NN * VB / 2];   // normalized visual_body fp16 (32 MB)
__device__ __half2 g_vnF[NN * VF / 2];   // normalized visual_face fp16 (8 MB)
__device__ float g_P0[DK], g_P1[DK];
__device__ float g_M1[DK], g_M2[DK], g_M3[DK];
__device__ float g_cst[12];
// edge sort scratch (counters zeroed by edge_kernel for next replay; zero at load)
__device__ int g_cntB[NN], g_cntF[NN];
__device__ int g_curB[NN], g_curF[NN];
__device__ int2 g_edB[NE], g_edF[NE];    // dst-sorted (src,dst)
__device__ float g_pad_[32];
__device__ volatile int g_flag = 0;      // constants ready
__device__ volatile int g_hist_done = 0; // hist blocks finished (target 64)
__device__ volatile int g_scan_done = 0; // scan blocks finished (target 2)

__device__ __forceinline__ float warpSum(float v) {
    #pragma unroll
    for (int o = 16; o; o >>= 1) v += __shfl_xor_sync(0xFFFFFFFFu, v, o);
    return v;
}

// ---------------- K1 grid layout (256 threads per block) ----------------
// 0                : precompute constants -> g_flag
// [1, 65)          : edge histograms (both graphs), bump g_hist_done
// [65, 67)         : exclusive scan of 8192 bins (spin hist), bump g_scan_done
// [67, 131)        : scatter edges into sorted order (spin scan)
// [131, 1155)      : body norm (warp/row, register prefetch)
// [1155, 2179)     : face norm (warp/row)
// [2179, 3203)     : attention + node (spin g_flag, dispatched last)
#define BLK_PRE    0
#define BLK_HIST   1
#define BLK_SCAN   (BLK_HIST + 64)
#define BLK_SCAT   (BLK_SCAN + 2)
#define BLK_NBODY  (BLK_SCAT + 64)
#define BLK_NFACE  (BLK_NBODY + 1024)
#define BLK_ATTN   (BLK_NFACE + 1024)
#define GRID_K1    (BLK_ATTN + 1024)

__global__ __launch_bounds__(256)
void norm_attn_kernel(const float* __restrict__ visB, const float* __restrict__ visF,
                      const float* __restrict__ x,
                      const float* __restrict__ ln_g, const float* __restrict__ ln_b,
                      const float* __restrict__ prelu_a,
                      const float* __restrict__ Wq, const float* __restrict__ Wk,
                      const float* __restrict__ Wv,
                      const float* __restrict__ mlp_W, const float* __restrict__ mlp_b,
                      const float* __restrict__ np_W, const float* __restrict__ np_b,
                      const float* __restrict__ body_W, const float* __restrict__ body_b,
                      const float* __restrict__ face_W, const float* __restrict__ face_b,
                      const float* __restrict__ pb_W, const float* __restrict__ pb_b,
                      const float* __restrict__ pf_W, const float* __restrict__ pf_b,
                      const int* __restrict__ eiB, const int* __restrict__ eiF,
                      float* __restrict__ out) {
    int b = blockIdx.x;
    int t = threadIdx.x;
    int lane = t & 31;
    int warp = t >> 5;

    if (b == BLK_PRE) {
        // ---------------- precompute constants ----------------
        __shared__ float sh_u2[HH], sh_u3[HH], sh_np[HH];
        __shared__ float sh_part[8][9];
        __shared__ float sh_res[12];
        int k1 = t, k2 = t + 256;

        if (t < HH) {
            float a2 = 0.f, a3 = 0.f;
            #pragma unroll
            for (int j = 0; j < HH; ++j) {
                a2 += body_W[t * HH + j] * pb_W[j];
                a3 += face_W[t * HH + j] * pf_W[j];
            }
            sh_u2[t] = a2;
            sh_u3[t] = a3;
            sh_np[t] = np_W[t];
        }

        float wq0a = Wq[k1], wq0b = Wq[k2], wq1a = Wq[DK + k1], wq1b = Wq[DK + k2];
        float wk0a = Wk[k1], wk0b = Wk[k2], wk1a = Wk[DK + k1], wk1b = Wk[DK + k2];
        float wv0a = Wv[k1], wv0b = Wv[k2], wv1a = Wv[DK + k1], wv1b = Wv[DK + k2];

        float v0 = warpSum(wq0a * wk0a + wq0b * wk0b);
        float v1 = warpSum(wq0a * wk1a + wq0b * wk1b);
        float v2 = warpSum(wq1a * wk0a + wq1b * wk0b);
        float v3 = warpSum(wq1a * wk1a + wq1b * wk1b);
        float v4 = warpSum(wv0a + wv0b);
        float v5 = warpSum(wv1a + wv1b);
        float v6 = warpSum(wv0a * wv0a + wv0b * wv0b);
        float v7 = warpSum(wv0a * wv1a + wv0b * wv1b);
        float v8 = warpSum(wv1a * wv1a + wv1b * wv1b);
        if (lane == 0) {
            sh_part[warp][0] = v0; sh_part[warp][1] = v1; sh_part[warp][2] = v2;
            sh_part[warp][3] = v3; sh_part[warp][4] = v4; sh_part[warp][5] = v5;
            sh_part[warp][6] = v6; sh_part[warp][7] = v7; sh_part[warp][8] = v8;
        }
        __syncthreads();

        if (warp == 0) {
            float mb = mlp_b[lane];
            float b1 = warpSum(mb * sh_np[lane]);
            float b2 = warpSum(mb * sh_u2[lane]);
            float b3 = warpSum(mb * sh_u3[lane]);
            float vBv = warpSum(body_b[lane] * pb_W[lane]);
            float vFv = warpSum(face_b[lane] * pf_W[lane]);
            if (lane == 0) {
                float r[9];
                #pragma unroll
                for (int i = 0; i < 9; ++i) {
                    float s = 0.f;
                    #pragma unroll
                    for (int w = 0; w < 8; ++w) s += sh_part[w][i];
                    r[i] = s;
                }
                float m0 = r[4] / (float)DK, m1 = r[5] / (float)DK;
                sh_res[0] = r[0]; sh_res[1] = r[1]; sh_res[2] = r[2]; sh_res[3] = r[3];
                sh_res[4] = r[6] / (float)DK - m0 * m0;
                sh_res[5] = r[7] / (float)DK - m0 * m1;
                sh_res[6] = r[8] / (float)DK - m1 * m1;
                sh_res[7] = b1 + np_b[0] + pb_b[0] + pf_b[0];
                sh_res[8] = b2 + vBv;
                sh_res[9] = b3 + vFv;
                sh_res[10] = m0;
                sh_res[11] = m1;
            }
        }
        __syncthreads();

        if (t < 12) g_cst[t] = sh_res[t];
        g_P0[k1] = wv0a - sh_res[10];
        g_P0[k2] = wv0b - sh_res[10];
        g_P1[k1] = wv1a - sh_res[11];
        g_P1[k2] = wv1b - sh_res[11];

        float a1a = 0.f, a2a = 0.f, a3a = 0.f, a1b = 0.f, a2b = 0.f, a3b = 0.f;
        #pragma unroll
        for (int l = 0; l < HH; ++l) {
            float wa = mlp_W[k1 * HH + l];
            float wb = mlp_W[k2 * HH + l];
            float un = sh_np[l], u2 = sh_u2[l], u3 = sh_u3[l];
            a1a += wa * un; a2a += wa * u2; a3a += wa * u3;
            a1b += wb * un; a2b += wb * u2; a3b += wb * u3;
        }
        g_M1[k1] = a1a; g_M2[k1] = a2a; g_M3[k1] = a3a;
        g_M1[k2] = a1b; g_M2[k2] = a2b; g_M3[k2] = a3b;

        __threadfence();
        __syncthreads();
        if (t == 0) g_flag = 1;
    } else if (b < BLK_SCAN) {
        // ---------------- edge histograms (both graphs) ----------------
        int h = b - BLK_HIST;            // 0..63
        #pragma unroll
        for (int i = 0; i < 4; ++i) {
            int e = h * 1024 + i * 256 + t;
            atomicAdd(&g_cntB[eiB[NE + e]], 1);
            atomicAdd(&g_cntF[eiF[NE + e]], 1);
        }
        __threadfence();
        __syncthreads();
        if (t == 0) atomicAdd((int*)&g_hist_done, 1);
    } else if (b < BLK_SCAT) {
        // ---------------- exclusive scan of 8192 bins (block 0: body, 1: face) ----------------
        __shared__ int sh[256];
        const int* cnt = (b == BLK_SCAN) ? g_cntB : g_cntF;
        int* cur = (b == BLK_SCAN) ? g_curB : g_curF;
        if (t == 0) {
            while (g_hist_done < 64) __nanosleep(128);
        }
        __syncthreads();
        __threadfence();
        int base = t * 32;
        int s = 0;
        #pragma unroll 8
        for (int i = 0; i < 32; ++i) s += cnt[base + i];
        sh[t] = s;
        __syncthreads();
        for (int o = 1; o < 256; o <<= 1) {
            int v = (t >= o) ? sh[t - o] : 0;
            __syncthreads();
            sh[t] += v;
            __syncthreads();
        }
        int excl = (t == 0) ? 0 : sh[t - 1];
        #pragma unroll 8
        for (int i = 0; i < 32; ++i) {
            cur[base + i] = excl;
            excl += cnt[base + i];
        }
        __threadfence();
        __syncthreads();
        if (t == 0) atomicAdd((int*)&g_scan_done, 1);
    } else if (b < BLK_NBODY) {
        // ---------------- scatter edges into dst-sorted order ----------------
        int h = b - BLK_SCAT;            // 0..63
        if (t == 0) {
            while (g_scan_done < 2) __nanosleep(128);
        }
        __syncthreads();
        __threadfence();
        #pragma unroll
        for (int i = 0; i < 4; ++i) {
            int e = h * 1024 + i * 256 + t;
            int srcB = eiB[e], dstB = eiB[NE + e];
            int pB = atomicAdd(&g_curB[dstB], 1);
            if (pB < NE) g_edB[pB] = make_int2(srcB, dstB);
            int srcF = eiF[e], dstF = eiF[NE + e];
            int pF = atomicAdd(&g_curF[dstF], 1);
            if (pF < NE) g_edF[pF] = make_int2(srcF, dstF);
        }
    } else if (b < BLK_NFACE) {
        // ---------------- body norm: warp per row, register prefetch ----------------
        int row = ((b - BLK_NBODY) * 256 + t) >> 5;
        const float4* v = reinterpret_cast<const float4*>(visB) + (size_t)row * (VB / 4) + lane;
        float4 r[16];
        #pragma unroll
        for (int i = 0; i < 16; ++i) r[i] = v[i * 32];
        float acc = 0.f;
        #pragma unroll
        for (int i = 0; i < 16; ++i)
            acc += r[i].x * r[i].x + r[i].y * r[i].y + r[i].z * r[i].z + r[i].w * r[i].w;
        acc = warpSum(acc);
        float rs = rsqrtf(acc + 1e-8f);
        uint2* o = reinterpret_cast<uint2*>(g_vnB) + (size_t)row * (VB / 4) + lane;
        #pragma unroll
        for (int i = 0; i < 16; ++i) {
            __half2 h0 = __floats2half2_rn(r[i].x * rs, r[i].y * rs);
            __half2 h1 = __floats2half2_rn(r[i].z * rs, r[i].w * rs);
            uint2 u;
            u.x = *reinterpret_cast<unsigned*>(&h0);
            u.y = *reinterpret_cast<unsigned*>(&h1);
            o[i * 32] = u;
        }
    } else if (b < BLK_ATTN) {
        // ---------------- face norm: warp per row ----------------
        int row = ((b - BLK_NFACE) * 256 + t) >> 5;
        const float4* v = reinterpret_cast<const float4*>(visF) + (size_t)row * (VF / 4) + lane;
        float4 r[4];
        #pragma unroll
        for (int i = 0; i < 4; ++i) r[i] = v[i * 32];
        float acc = 0.f;
        #pragma unroll
        for (int i = 0; i < 4; ++i)
            acc += r[i].x * r[i].x + r[i].y * r[i].y + r[i].z * r[i].z + r[i].w * r[i].w;
        acc = warpSum(acc);
        float rs = rsqrtf(acc + 1e-8f);
        uint2* o = reinterpret_cast<uint2*>(g_vnF) + (size_t)row * (VF / 4) + lane;
        #pragma unroll
        for (int i = 0; i < 4; ++i) {
            __half2 h0 = __floats2half2_rn(r[i].x * rs, r[i].y * rs);
            __half2 h1 = __floats2half2_rn(r[i].z * rs, r[i].w * rs);
            uint2 u;
            u.x = *reinterpret_cast<unsigned*>(&h0);
            u.y = *reinterpret_cast<unsigned*>(&h1);
            o[i * 32] = u;
        }
    } else {
        // ---------------- attention + node stage (spin g_flag, dispatched last) ----------------
        __shared__ float sa[NG], sb[NG];
        int idx = b - BLK_ATTN;
        int g = idx >> 5;
        int bi = idx & 31;
        int node = g * NG + t;
        sa[t] = x[2 * node];
        sb[t] = x[2 * node + 1];
        if (t == 0) {
            while (g_flag == 0) __nanosleep(64);
        }
        __syncthreads();
        __threadfence();

        float g00 = g_cst[0], g01 = g_cst[1], g10 = g_cst[2], g11 = g_cst[3];
        const float inv = 0.04419417382415922f;
        int i = bi * 8 + warp;

        float ai = sa[i], bi2 = sb[i];
        float alpha = (ai * g00 + bi2 * g10) * inv;
        float beta  = (ai * g01 + bi2 * g11) * inv;
        float m = -1e30f;
        #pragma unroll
        for (int j = lane; j < NG; j += 32)
            m = fmaxf(m, alpha * sa[j] + beta * sb[j]);
        #pragma unroll
        for (int o = 16; o; o >>= 1) m = fmaxf(m, __shfl_xor_sync(0xFFFFFFFFu, m, o));
        float s = 0.f, sA = 0.f, sBv = 0.f;
        #pragma unroll
        for (int j = lane; j < NG; j += 32) {
            float e = __expf(alpha * sa[j] + beta * sb[j] - m);
            s += e; sA += e * sa[j]; sBv += e * sb[j];
        }
        s = warpSum(s); sA = warpSum(sA); sBv = warpSum(sBv);
        float c = sA / s, d = sBv / s;

        float s00 = g_cst[4], s01 = g_cst[5], s11 = g_cst[6];
        float var = c * c * s00 + 2.f * c * d * s01 + d * d * s11;
        float rstd = rsqrtf(var + EPS);
        float a = prelu_a[0];
        float acc1 = 0.f, acc2 = 0.f, acc3 = 0.f;
        #pragma unroll 4
        for (int k = lane; k < DK; k += 32) {
            float z = (c * g_P0[k] + d * g_P1[k]) * rstd;
            float tv = z * ln_g[k] + ln_b[k];
            tv = tv >= 0.f ? tv : a * tv;
            acc1 += tv * g_M1[k];
            acc2 += tv * g_M2[k];
            acc3 += tv * g_M3[k];
        }
        acc1 = warpSum(acc1); acc2 = warpSum(acc2); acc3 = warpSum(acc3);
        if (lane == 0) {
            int n = g * NG + i;
            out[n]  = acc1 + g_cst[7];
            g_sB[n] = acc2 + g_cst[8];
            g_sF[n] = acc3 + g_cst[9];
        }
    }
}

// ---------------- K_edge: dst-sorted, deep prefetch, HFMA2 inner product ----------------
#define EDGE_TPB 128
#define BODY_WARPS NE                 // 65536 warps
#define FACE_WARPS (NE / 2)           // 32768 warps
#define BODY_BLOCKS (BODY_WARPS * 32 / EDGE_TPB)   // 16384
#define FACE_BLOCKS (FACE_WARPS * 32 / EDGE_TPB)   // 8192

__global__ void edge_kernel(float* __restrict__ out) {
    // reset sync state + bin counters for the next graph replay
    if (blockIdx.x < 64) {
        int i = blockIdx.x * EDGE_TPB + threadIdx.x;   // 8192 threads
        g_cntB[i] = 0;
        g_cntF[i] = 0;
        if (i == 0) { g_flag = 0; g_hist_done = 0; g_scan_done = 0; }
    }

    int gw = (blockIdx.x * EDGE_TPB + threadIdx.x) >> 5;
    int lane = threadIdx.x & 31;

    if (gw < BODY_WARPS) {
        int2 ed = g_edB[gw];
        int src = ed.x, dst = ed.y;
        const int4* a = reinterpret_cast<const int4*>(g_vnB) + (size_t)src * (VB / 8) + lane;
        const int4* b = reinterpret_cast<const int4*>(g_vnB) + (size_t)dst * (VB / 8) + lane;
        int4 ra[8], rb[8];
        #pragma unroll
        for (int i = 0; i < 8; ++i) ra[i] = a[i * 32];
        #pragma unroll
        for (int i = 0; i < 8; ++i) rb[i] = b[i * 32];
        float acc = 0.f;
        #pragma unroll
        for (int i = 0; i < 8; ++i) {
            const __half2* ha = reinterpret_cast<const __half2*>(&ra[i]);
            const __half2* hb = reinterpret_cast<const __half2*>(&rb[i]);
            __half2 h = __hmul2(ha[0], hb[0]);
            h = __hfma2(ha[1], hb[1], h);
            h = __hfma2(ha[2], hb[2], h);
            h = __hfma2(ha[3], hb[3], h);
            float2 f = __half22float2(h);
            acc += f.x + f.y;
        }
        acc = warpSum(acc);
        if (lane == 0) atomicAdd(&out[dst], acc * g_sB[src]);
    } else {
        int e = (gw - BODY_WARPS) * 2 + (lane >> 4);
        int hl = lane & 15;
        int2 ed = g_edF[e];
        int src = ed.x, dst = ed.y;
        const int4* a = reinterpret_cast<const int4*>(g_vnF) + (size_t)src * (VF / 8) + hl;
        const int4* b = reinterpret_cast<const int4*>(g_vnF) + (size_t)dst * (VF / 8) + hl;
        int4 ra[4], rb[4];
        #pragma unroll
        for (int i = 0; i < 4; ++i) ra[i] = a[i * 16];
        #pragma unroll
        for (int i = 0; i < 4; ++i) rb[i] = b[i * 16];
        float acc = 0.f;
        #pragma unroll
        for (int i = 0; i < 4; ++i) {
            const __half2* ha = reinterpret_cast<const __half2*>(&ra[i]);
            const __half2* hb = reinterpret_cast<const __half2*>(&rb[i]);
            __half2 h = __hmul2(ha[0], hb[0]);
            h = __hfma2(ha[1], hb[1], h);
            h = __hfma2(ha[2], hb[2], h);
            h = __hfma2(ha[3], hb[3], h);
            float2 f = __half22float2(h);
            acc += f.x + f.y;
        }
        #pragma unroll
        for (int o = 8; o; o >>= 1) acc += __shfl_xor_sync(0xFFFFFFFFu, acc, o);
        if (hl == 0) atomicAdd(&out[dst], acc * g_sF[src]);
    }
}

// ---------------- launch ----------------
extern "C" void kernel_launch(void* const* d_in, const int* in_sizes, int n_in,
                              void* d_out, int out_size) {
    const float* x           = (const float*)d_in[0];
    const float* visual_body = (const float*)d_in[1];
    const float* visual_face = (const float*)d_in[2];
    const float* Wq          = (const float*)d_in[3];
    const float* Wk          = (const float*)d_in[4];
    const float* Wv          = (const float*)d_in[5];
    const float* ln_g        = (const float*)d_in[6];
    const float* ln_b        = (const float*)d_in[7];
    const float* prelu_a     = (const float*)d_in[8];
    const float* mlp_W       = (const float*)d_in[9];
    const float* mlp_b       = (const float*)d_in[10];
    const float* np_W        = (const float*)d_in[11];
    const float* np_b        = (const float*)d_in[12];
    const float* body_W      = (const float*)d_in[13];
    const float* body_b      = (const float*)d_in[14];
    const float* face_W      = (const float*)d_in[15];
    const float* face_b      = (const float*)d_in[16];
    const float* pb_W        = (const float*)d_in[17];
    const float* pb_b        = (const float*)d_in[18];
    const float* pf_W        = (const float*)d_in[19];
    const float* pf_b        = (const float*)d_in[20];
    const int*   ei_body     = (const int*)d_in[21];
    const int*   ei_face     = (const int*)d_in[22];
    float* out = (float*)d_out;

    norm_attn_kernel<<<GRID_K1, 256>>>(
        visual_body, visual_face, x, ln_g, ln_b, prelu_a,
        Wq, Wk, Wv, mlp_W, mlp_b, np_W, np_b,
        body_W, body_b, face_W, face_b, pb_W, pb_b, pf_W, pf_b,
        ei_body, ei_face, out);

    edge_kernel<<<BODY_BLOCKS + FACE_BLOCKS, EDGE_TPB>>>(out);
}

// round 15
// speedup vs baseline: 1.3942x; 1.0284x over previous
#include <cuda_runtime.h>
#include <cuda_fp16.h>
#include <math.h>

#define NN 8192
#define NB 32
#define NG 256
#define NE 65536
#define DK 512
#define HH 32
#define VB 2048
#define VF 512
#define EPS 1e-5f

// ---------------- device scratch ----------------
__device__ float g_sB[NN], g_sF[NN];
__device__ __half2 g_vnB[NN * VB / 2];   // normalized visual_body fp16 (32 MB)
__device__ __half2 g_vnF[NN * VF / 2];   // normalized visual_face fp16 (8 MB)
__device__ float g_P0[DK], g_P1[DK];
__device__ float g_M1[DK], g_M2[DK], g_M3[DK];
__device__ float g_cst[12];
// edge sort scratch (counters zeroed by edge_kernel for next replay; zero at load)
__device__ int g_cntB[NN], g_cntF[NN];
__device__ int g_curB[NN], g_curF[NN];
__device__ int2 g_edB[NE], g_edF[NE];    // dst-sorted (src,dst)
__device__ float g_pad_[32];
__device__ volatile int g_flag = 0;      // constants ready
__device__ volatile int g_hist_done = 0; // hist blocks finished (target 64)
__device__ volatile int g_scan_done = 0; // scan blocks finished (target 2)

__device__ __forceinline__ float warpSum(float v) {
    #pragma unroll
    for (int o = 16; o; o >>= 1) v += __shfl_xor_sync(0xFFFFFFFFu, v, o);
    return v;
}

// ---------------- K1 grid layout (256 threads per block) ----------------
// 0                : precompute constants -> g_flag
// [1, 65)          : edge histograms (both graphs), bump g_hist_done
// [65, 67)         : exclusive scan of 8192 bins (spin hist), bump g_scan_done
// [67, 131)        : scatter edges into sorted order (spin scan)
// [131, 1155)      : body norm (warp/row, register prefetch)
// [1155, 2179)     : face norm (warp/row)
// [2179, 3203)     : attention + node (spin g_flag, dispatched last)
#define BLK_PRE    0
#define BLK_HIST   1
#define BLK_SCAN   (BLK_HIST + 64)
#define BLK_SCAT   (BLK_SCAN + 2)
#define BLK_NBODY  (BLK_SCAT + 64)
#define BLK_NFACE  (BLK_NBODY + 1024)
#define BLK_ATTN   (BLK_NFACE + 1024)
#define GRID_K1    (BLK_ATTN + 1024)

__global__ __launch_bounds__(256)
void norm_attn_kernel(const float* __restrict__ visB, const float* __restrict__ visF,
                      const float* __restrict__ x,
                      const float* __restrict__ ln_g, const float* __restrict__ ln_b,
                      const float* __restrict__ prelu_a,
                      const float* __restrict__ Wq, const float* __restrict__ Wk,
                      const float* __restrict__ Wv,
                      const float* __restrict__ mlp_W, const float* __restrict__ mlp_b,
                      const float* __restrict__ np_W, const float* __restrict__ np_b,
                      const float* __restrict__ body_W, const float* __restrict__ body_b,
                      const float* __restrict__ face_W, const float* __restrict__ face_b,
                      const float* __restrict__ pb_W, const float* __restrict__ pb_b,
                      const float* __restrict__ pf_W, const float* __restrict__ pf_b,
                      const int* __restrict__ eiB, const int* __restrict__ eiF,
                      float* __restrict__ out) {
    int b = blockIdx.x;
    int t = threadIdx.x;
    int lane = t & 31;
    int warp = t >> 5;

    if (b == BLK_PRE) {
        // ---------------- precompute constants ----------------
        __shared__ float sh_u2[HH], sh_u3[HH], sh_np[HH];
        __shared__ float sh_part[8][9];
        __shared__ float sh_res[12];
        int k1 = t, k2 = t + 256;

        if (t < HH) {
            float a2 = 0.f, a3 = 0.f;
            #pragma unroll
            for (int j = 0; j < HH; ++j) {
                a2 += body_W[t * HH + j] * pb_W[j];
                a3 += face_W[t * HH + j] * pf_W[j];
            }
            sh_u2[t] = a2;
            sh_u3[t] = a3;
            sh_np[t] = np_W[t];
        }

        float wq0a = Wq[k1], wq0b = Wq[k2], wq1a = Wq[DK + k1], wq1b = Wq[DK + k2];
        float wk0a = Wk[k1], wk0b = Wk[k2], wk1a = Wk[DK + k1], wk1b = Wk[DK + k2];
        float wv0a = Wv[k1], wv0b = Wv[k2], wv1a = Wv[DK + k1], wv1b = Wv[DK + k2];

        float v0 = warpSum(wq0a * wk0a + wq0b * wk0b);
        float v1 = warpSum(wq0a * wk1a + wq0b * wk1b);
        float v2 = warpSum(wq1a * wk0a + wq1b * wk0b);
        float v3 = warpSum(wq1a * wk1a + wq1b * wk1b);
        float v4 = warpSum(wv0a + wv0b);
        float v5 = warpSum(wv1a + wv1b);
        float v6 = warpSum(wv0a * wv0a + wv0b * wv0b);
        float v7 = warpSum(wv0a * wv1a + wv0b * wv1b);
        float v8 = warpSum(wv1a * wv1a + wv1b * wv1b);
        if (lane == 0) {
            sh_part[warp][0] = v0; sh_part[warp][1] = v1; sh_part[warp][2] = v2;
            sh_part[warp][3] = v3; sh_part[warp][4] = v4; sh_part[warp][5] = v5;
            sh_part[warp][6] = v6; sh_part[warp][7] = v7; sh_part[warp][8] = v8;
        }
        __syncthreads();

        if (warp == 0) {
            float mb = mlp_b[lane];
            float b1 = warpSum(mb * sh_np[lane]);
            float b2 = warpSum(mb * sh_u2[lane]);
            float b3 = warpSum(mb * sh_u3[lane]);
            float vBv = warpSum(body_b[lane] * pb_W[lane]);
            float vFv = warpSum(face_b[lane] * pf_W[lane]);
            if (lane == 0) {
                float r[9];
                #pragma unroll
                for (int i = 0; i < 9; ++i) {
                    float s = 0.f;
                    #pragma unroll
                    for (int w = 0; w < 8; ++w) s += sh_part[w][i];
                    r[i] = s;
                }
                float m0 = r[4] / (float)DK, m1 = r[5] / (float)DK;
                sh_res[0] = r[0]; sh_res[1] = r[1]; sh_res[2] = r[2]; sh_res[3] = r[3];
                sh_res[4] = r[6] / (float)DK - m0 * m0;
                sh_res[5] = r[7] / (float)DK - m0 * m1;
                sh_res[6] = r[8] / (float)DK - m1 * m1;
                sh_res[7] = b1 + np_b[0] + pb_b[0] + pf_b[0];
                sh_res[8] = b2 + vBv;
                sh_res[9] = b3 + vFv;
                sh_res[10] = m0;
                sh_res[11] = m1;
            }
        }
        __syncthreads();

        if (t < 12) g_cst[t] = sh_res[t];
        g_P0[k1] = wv0a - sh_res[10];
        g_P0[k2] = wv0b - sh_res[10];
        g_P1[k1] = wv1a - sh_res[11];
        g_P1[k2] = wv1b - sh_res[11];

        float a1a = 0.f, a2a = 0.f, a3a = 0.f, a1b = 0.f, a2b = 0.f, a3b = 0.f;
        #pragma unroll
        for (int l = 0; l < HH; ++l) {
            float wa = mlp_W[k1 * HH + l];
            float wb = mlp_W[k2 * HH + l];
            float un = sh_np[l], u2 = sh_u2[l], u3 = sh_u3[l];
            a1a += wa * un; a2a += wa * u2; a3a += wa * u3;
            a1b += wb * un; a2b += wb * u2; a3b += wb * u3;
        }
        g_M1[k1] = a1a; g_M2[k1] = a2a; g_M3[k1] = a3a;
        g_M1[k2] = a1b; g_M2[k2] = a2b; g_M3[k2] = a3b;

        __threadfence();
        __syncthreads();
        if (t == 0) g_flag = 1;
    } else if (b < BLK_SCAN) {
        // ---------------- edge histograms (both graphs) ----------------
        int h = b - BLK_HIST;            // 0..63
        #pragma unroll
        for (int i = 0; i < 4; ++i) {
            int e = h * 1024 + i * 256 + t;
            atomicAdd(&g_cntB[eiB[NE + e]], 1);
            atomicAdd(&g_cntF[eiF[NE + e]], 1);
        }
        __threadfence();
        __syncthreads();
        if (t == 0) atomicAdd((int*)&g_hist_done, 1);
    } else if (b < BLK_SCAT) {
        // ---------------- exclusive scan of 8192 bins (block 0: body, 1: face) ----------------
        __shared__ int sh[256];
        const int* cnt = (b == BLK_SCAN) ? g_cntB : g_cntF;
        int* cur = (b == BLK_SCAN) ? g_curB : g_curF;
        if (t == 0) {
            while (g_hist_done < 64) __nanosleep(128);
        }
        __syncthreads();
        __threadfence();
        int base = t * 32;
        int s = 0;
        #pragma unroll 8
        for (int i = 0; i < 32; ++i) s += cnt[base + i];
        sh[t] = s;
        __syncthreads();
        for (int o = 1; o < 256; o <<= 1) {
            int v = (t >= o) ? sh[t - o] : 0;
            __syncthreads();
            sh[t] += v;
            __syncthreads();
        }
        int excl = (t == 0) ? 0 : sh[t - 1];
        #pragma unroll 8
        for (int i = 0; i < 32; ++i) {
            cur[base + i] = excl;
            excl += cnt[base + i];
        }
        __threadfence();
        __syncthreads();
        if (t == 0) atomicAdd((int*)&g_scan_done, 1);
    } else if (b < BLK_NBODY) {
        // ---------------- scatter edges into dst-sorted order ----------------
        int h = b - BLK_SCAT;            // 0..63
        if (t == 0) {
            while (g_scan_done < 2) __nanosleep(128);
        }
        __syncthreads();
        __threadfence();
        #pragma unroll
        for (int i = 0; i < 4; ++i) {
            int e = h * 1024 + i * 256 + t;
            int srcB = eiB[e], dstB = eiB[NE + e];
            int pB = atomicAdd(&g_curB[dstB], 1);
            if (pB < NE) g_edB[pB] = make_int2(srcB, dstB);
            int srcF = eiF[e], dstF = eiF[NE + e];
            int pF = atomicAdd(&g_curF[dstF], 1);
            if (pF < NE) g_edF[pF] = make_int2(srcF, dstF);
        }
    } else if (b < BLK_NFACE) {
        // ---------------- body norm: warp per row, register prefetch ----------------
        int row = ((b - BLK_NBODY) * 256 + t) >> 5;
        const float4* v = reinterpret_cast<const float4*>(visB) + (size_t)row * (VB / 4) + lane;
        float4 r[16];
        #pragma unroll
        for (int i = 0; i < 16; ++i) r[i] = v[i * 32];
        float acc = 0.f;
        #pragma unroll
        for (int i = 0; i < 16; ++i)
            acc += r[i].x * r[i].x + r[i].y * r[i].y + r[i].z * r[i].z + r[i].w * r[i].w;
        acc = warpSum(acc);
        float rs = rsqrtf(acc + 1e-8f);
        uint2* o = reinterpret_cast<uint2*>(g_vnB) + (size_t)row * (VB / 4) + lane;
        #pragma unroll
        for (int i = 0; i < 16; ++i) {
            __half2 h0 = __floats2half2_rn(r[i].x * rs, r[i].y * rs);
            __half2 h1 = __floats2half2_rn(r[i].z * rs, r[i].w * rs);
            uint2 u;
            u.x = *reinterpret_cast<unsigned*>(&h0);
            u.y = *reinterpret_cast<unsigned*>(&h1);
            o[i * 32] = u;
        }
    } else if (b < BLK_ATTN) {
        // ---------------- face norm: warp per row ----------------
        int row = ((b - BLK_NFACE) * 256 + t) >> 5;
        const float4* v = reinterpret_cast<const float4*>(visF) + (size_t)row * (VF / 4) + lane;
        float4 r[4];
        #pragma unroll
        for (int i = 0; i < 4; ++i) r[i] = v[i * 32];
        float acc = 0.f;
        #pragma unroll
        for (int i = 0; i < 4; ++i)
            acc += r[i].x * r[i].x + r[i].y * r[i].y + r[i].z * r[i].z + r[i].w * r[i].w;
        acc = warpSum(acc);
        float rs = rsqrtf(acc + 1e-8f);
        uint2* o = reinterpret_cast<uint2*>(g_vnF) + (size_t)row * (VF / 4) + lane;
        #pragma unroll
        for (int i = 0; i < 4; ++i) {
            __half2 h0 = __floats2half2_rn(r[i].x * rs, r[i].y * rs);
            __half2 h1 = __floats2half2_rn(r[i].z * rs, r[i].w * rs);
            uint2 u;
            u.x = *reinterpret_cast<unsigned*>(&h0);
            u.y = *reinterpret_cast<unsigned*>(&h1);
            o[i * 32] = u;
        }
    } else {
        // ---------------- attention + node stage (spin g_flag, dispatched last) ----------------
        __shared__ float sa[NG], sb[NG];
        int idx = b - BLK_ATTN;
        int g = idx >> 5;
        int bi = idx & 31;
        int node = g * NG + t;
        sa[t] = x[2 * node];
        sb[t] = x[2 * node + 1];
        if (t == 0) {
            while (g_flag == 0) __nanosleep(64);
        }
        __syncthreads();
        __threadfence();

        float g00 = g_cst[0], g01 = g_cst[1], g10 = g_cst[2], g11 = g_cst[3];
        const float inv = 0.04419417382415922f;
        int i = bi * 8 + warp;

        float ai = sa[i], bi2 = sb[i];
        float alpha = (ai * g00 + bi2 * g10) * inv;
        float beta  = (ai * g01 + bi2 * g11) * inv;
        float m = -1e30f;
        #pragma unroll
        for (int j = lane; j < NG; j += 32)
            m = fmaxf(m, alpha * sa[j] + beta * sb[j]);
        #pragma unroll
        for (int o = 16; o; o >>= 1) m = fmaxf(m, __shfl_xor_sync(0xFFFFFFFFu, m, o));
        float s = 0.f, sA = 0.f, sBv = 0.f;
        #pragma unroll
        for (int j = lane; j < NG; j += 32) {
            float e = __expf(alpha * sa[j] + beta * sb[j] - m);
            s += e; sA += e * sa[j]; sBv += e * sb[j];
        }
        s = warpSum(s); sA = warpSum(sA); sBv = warpSum(sBv);
        float c = sA / s, d = sBv / s;

        float s00 = g_cst[4], s01 = g_cst[5], s11 = g_cst[6];
        float var = c * c * s00 + 2.f * c * d * s01 + d * d * s11;
        float rstd = rsqrtf(var + EPS);
        float a = prelu_a[0];
        float acc1 = 0.f, acc2 = 0.f, acc3 = 0.f;
        #pragma unroll 4
        for (int k = lane; k < DK; k += 32) {
            float z = (c * g_P0[k] + d * g_P1[k]) * rstd;
            float tv = z * ln_g[k] + ln_b[k];
            tv = tv >= 0.f ? tv : a * tv;
            acc1 += tv * g_M1[k];
            acc2 += tv * g_M2[k];
            acc3 += tv * g_M3[k];
        }
        acc1 = warpSum(acc1); acc2 = warpSum(acc2); acc3 = warpSum(acc3);
        if (lane == 0) {
            int n = g * NG + i;
            out[n]  = acc1 + g_cst[7];
            g_sB[n] = acc2 + g_cst[8];
            g_sF[n] = acc3 + g_cst[9];
        }
    }
}

// ---------------- K_edge: dst-sorted, deep prefetch, FFMA inner product (R13 proven 32.5us) ----------------
#define EDGE_TPB 128
#define BODY_WARPS NE                 // 65536 warps
#define FACE_WARPS (NE / 2)           // 32768 warps
#define BODY_BLOCKS (BODY_WARPS * 32 / EDGE_TPB)   // 16384
#define FACE_BLOCKS (FACE_WARPS * 32 / EDGE_TPB)   // 8192

__global__ void edge_kernel(float* __restrict__ out) {
    // reset sync state + bin counters for the next graph replay
    if (blockIdx.x < 64) {
        int i = blockIdx.x * EDGE_TPB + threadIdx.x;   // 8192 threads
        g_cntB[i] = 0;
        g_cntF[i] = 0;
        if (i == 0) { g_flag = 0; g_hist_done = 0; g_scan_done = 0; }
    }

    int gw = (blockIdx.x * EDGE_TPB + threadIdx.x) >> 5;
    int lane = threadIdx.x & 31;

    if (gw < BODY_WARPS) {
        int2 ed = g_edB[gw];
        int src = ed.x, dst = ed.y;
        const int4* a = reinterpret_cast<const int4*>(g_vnB) + (size_t)src * (VB / 8) + lane;
        const int4* b = reinterpret_cast<const int4*>(g_vnB) + (size_t)dst * (VB / 8) + lane;
        int4 ra[8], rb[8];
        #pragma unroll
        for (int i = 0; i < 8; ++i) ra[i] = a[i * 32];
        #pragma unroll
        for (int i = 0; i < 8; ++i) rb[i] = b[i * 32];
        float acc0 = 0.f, acc1 = 0.f;
        #pragma unroll
        for (int i = 0; i < 8; ++i) {
            const __half2* ha = reinterpret_cast<const __half2*>(&ra[i]);
            const __half2* hb = reinterpret_cast<const __half2*>(&rb[i]);
            #pragma unroll
            for (int u = 0; u < 4; ++u) {
                float2 fa = __half22float2(ha[u]);
                float2 fb = __half22float2(hb[u]);
                acc0 += fa.x * fb.x;
                acc1 += fa.y * fb.y;
            }
        }
        float acc = warpSum(acc0 + acc1);
        if (lane == 0) atomicAdd(&out[dst], acc * g_sB[src]);
    } else {
        int e = (gw - BODY_WARPS) * 2 + (lane >> 4);
        int hl = lane & 15;
        int2 ed = g_edF[e];
        int src = ed.x, dst = ed.y;
        const int4* a = reinterpret_cast<const int4*>(g_vnF) + (size_t)src * (VF / 8) + hl;
        const int4* b = reinterpret_cast<const int4*>(g_vnF) + (size_t)dst * (VF / 8) + hl;
        int4 ra[4], rb[4];
        #pragma unroll
        for (int i = 0; i < 4; ++i) ra[i] = a[i * 16];
        #pragma unroll
        for (int i = 0; i < 4; ++i) rb[i] = b[i * 16];
        float acc0 = 0.f, acc1 = 0.f;
        #pragma unroll
        for (int i = 0; i < 4; ++i) {
            const __half2* ha = reinterpret_cast<const __half2*>(&ra[i]);
            const __half2* hb = reinterpret_cast<const __half2*>(&rb[i]);
            #pragma unroll
            for (int u = 0; u < 4; ++u) {
                float2 fa = __half22float2(ha[u]);
                float2 fb = __half22float2(hb[u]);
                acc0 += fa.x * fb.x;
                acc1 += fa.y * fb.y;
            }
        }
        float acc = acc0 + acc1;
        #pragma unroll
        for (int o = 8; o; o >>= 1) acc += __shfl_xor_sync(0xFFFFFFFFu, acc, o);
        if (hl == 0) atomicAdd(&out[dst], acc * g_sF[src]);
    }
}

// ---------------- launch ----------------
extern "C" void kernel_launch(void* const* d_in, const int* in_sizes, int n_in,
                              void* d_out, int out_size) {
    const float* x           = (const float*)d_in[0];
    const float* visual_body = (const float*)d_in[1];
    const float* visual_face = (const float*)d_in[2];
    const float* Wq          = (const float*)d_in[3];
    const float* Wk          = (const float*)d_in[4];
    const float* Wv          = (const float*)d_in[5];
    const float* ln_g        = (const float*)d_in[6];
    const float* ln_b        = (const float*)d_in[7];
    const float* prelu_a     = (const float*)d_in[8];
    const float* mlp_W       = (const float*)d_in[9];
    const float* mlp_b       = (const float*)d_in[10];
    const float* np_W        = (const float*)d_in[11];
    const float* np_b        = (const float*)d_in[12];
    const float* body_W      = (const float*)d_in[13];
    const float* body_b      = (const float*)d_in[14];
    const float* face_W      = (const float*)d_in[15];
    const float* face_b      = (const float*)d_in[16];
    const float* pb_W        = (const float*)d_in[17];
    const float* pb_b        = (const float*)d_in[18];
    const float* pf_W        = (const float*)d_in[19];
    const float* pf_b        = (const float*)d_in[20];
    const int*   ei_body     = (const int*)d_in[21];
    const int*   ei_face     = (const int*)d_in[22];
    float* out = (float*)d_out;

    norm_attn_kernel<<<GRID_K1, 256>>>(
        visual_body, visual_face, x, ln_g, ln_b, prelu_a,
        Wq, Wk, Wv, mlp_W, mlp_b, np_W, np_b,
        body_W, body_b, face_W, face_b, pb_W, pb_b, pf_W, pf_b,
        ei_body, ei_face, out);

    edge_kernel<<<BODY_BLOCKS + FACE_BLOCKS, EDGE_TPB>>>(out);
}